// round 8
// baseline (speedup 1.0000x reference)
#include <cuda_runtime.h>
#include <math.h>

#define BB   64
#define TT   512
#define IND  256
#define HH   1024
#define OUTD 256

#define NCTA 128
#define COLS 8
#define RSTR 68

// -------- device scratch --------
__device__ float g_xh[TT * BB * HH];   // [t][j][b]
__device__ float g_xz[TT * BB * HH];
__device__ float g_xr[TT * BB * HH];
__device__ float g_hP [HH * BB];       // h   fragment-packed (tf32 bits)
__device__ float g_hrP[HH * BB];       // h*r fragment-packed (tf32 bits)
__device__ float g_hT [HH * BB];       // plain [j][b], final step only
__device__ unsigned g_flags[NCTA];     // per-CTA barrier generation

// -------- helpers --------
__device__ __forceinline__ unsigned cvt_tf32(float x) {
    unsigned r; asm("cvt.rna.tf32.f32 %0, %1;" : "=r"(r) : "f"(x)); return r;
}
__device__ __forceinline__ void mma8(float (&d)[4], const unsigned (&a)[4], const unsigned (&b)[2]) {
    asm volatile("mma.sync.aligned.m16n8k8.row.col.f32.tf32.tf32.f32 "
                 "{%0,%1,%2,%3}, {%4,%5,%6,%7}, {%8,%9}, {%0,%1,%2,%3};"
                 : "+f"(d[0]), "+f"(d[1]), "+f"(d[2]), "+f"(d[3])
                 : "r"(a[0]), "r"(a[1]), "r"(a[2]), "r"(a[3]), "r"(b[0]), "r"(b[1]));
}
__device__ __forceinline__ float sigm_(float x) { return 1.0f / (1.0f + __expf(-x)); }

__device__ __forceinline__ unsigned long long splat2(float x) {
    unsigned long long r; asm("mov.b64 %0, {%1, %1};" : "=l"(r) : "f"(x)); return r;
}
__device__ __forceinline__ unsigned long long pack2(float x, float y) {
    unsigned long long r; asm("mov.b64 %0, {%1, %2};" : "=l"(r) : "f"(x), "f"(y)); return r;
}
__device__ __forceinline__ void fma2(unsigned long long& d, unsigned long long a, unsigned long long b) {
    asm("fma.rn.f32x2 %0, %1, %2, %0;" : "+l"(d) : "l"(a), "l"(b));
}
__device__ __forceinline__ float2 unpack2(unsigned long long v) {
    float2 f; asm("mov.b64 {%0, %1}, %2;" : "=f"(f.x), "=f"(f.y) : "l"(v)); return f;
}

// -------- grid barrier: flag array, release/acquire, tight spin --------
__device__ __forceinline__ void gsync(unsigned gen) {
    __syncthreads();
    if (threadIdx.x == 0)
        asm volatile("st.release.gpu.global.u32 [%0], %1;"
                     :: "l"(g_flags + blockIdx.x), "r"(gen) : "memory");
    if (threadIdx.x < NCTA) {
        unsigned v;
        do {
            asm volatile("ld.acquire.gpu.global.u32 %0, [%1];"
                         : "=r"(v) : "l"(g_flags + threadIdx.x) : "memory");
        } while (v < gen);
    }
    __syncthreads();
}

// -------- kernel 1: input projections --------
__global__ __launch_bounds__(256) void proj_kernel(
    const float* __restrict__ X,
    const float* __restrict__ W0, const float* __restrict__ W1, const float* __restrict__ W2,
    const float* __restrict__ b0, const float* __restrict__ b1, const float* __restrict__ b2)
{
    __shared__ float As[32][68];
    __shared__ float Bs[32][68];

    const int z = blockIdx.z;
    const float* W    = (z == 0) ? W0 : (z == 1) ? W1 : W2;
    const float* bias = (z == 0) ? b0 : (z == 1) ? b1 : b2;
    float*       outp = (z == 0) ? g_xh : (z == 1) ? g_xz : g_xr;

    const int t   = blockIdx.y;
    const int j0  = blockIdx.x * 64;
    const int tid = threadIdx.x;
    const int ty  = tid >> 4;
    const int tx  = tid & 15;

    unsigned long long acc2[4][2];
#pragma unroll
    for (int i = 0; i < 4; i++) { acc2[i][0] = 0ull; acc2[i][1] = 0ull; }

    for (int kt = 0; kt < IND; kt += 32) {
#pragma unroll
        for (int l = 0; l < 8; l++) {
            int flat = tid + l * 256;
            int row = flat >> 5, col = flat & 31;
            As[col][row] = W[(j0 + row) * IND + kt + col];
            Bs[col][row] = X[row * (TT * IND) + t * IND + kt + col];
        }
        __syncthreads();
#pragma unroll
        for (int kk = 0; kk < 32; kk++) {
            float4 a4 = *reinterpret_cast<const float4*>(&As[kk][ty * 4]);
            float4 b4 = *reinterpret_cast<const float4*>(&Bs[kk][tx * 4]);
            unsigned long long p01 = pack2(b4.x, b4.y);
            unsigned long long p23 = pack2(b4.z, b4.w);
            float a[4] = { a4.x, a4.y, a4.z, a4.w };
#pragma unroll
            for (int i = 0; i < 4; i++) {
                unsigned long long aa = splat2(a[i]);
                fma2(acc2[i][0], aa, p01);
                fma2(acc2[i][1], aa, p23);
            }
        }
        __syncthreads();
    }
#pragma unroll
    for (int i = 0; i < 4; i++) {
        int j = j0 + ty * 4 + i;
        float bvv = bias[j];
        float2 p0 = unpack2(acc2[i][0]);
        float2 p1 = unpack2(acc2[i][1]);
        float4 v = make_float4(p0.x + bvv, p0.y + bvv, p1.x + bvv, p1.y + bvv);
        *reinterpret_cast<float4*>(&outp[t * (HH * BB) + j * BB + tx * 4]) = v;
    }
}

// -------- kernel 2: persistent scan (tf32 mma, 128 CTAs x 8 cols) --------
__global__ __launch_bounds__(256, 1) void scan_kernel(
    const float* __restrict__ Wh, const float* __restrict__ Vz, const float* __restrict__ Vr)
{
    extern __shared__ float smem[];
    float* Bp   = smem;                 // 3*128*64 = 24576 floats (weight frags)
    float* redz = smem + 24576;         // 64*RSTR
    float* redr = redz + 64 * RSTR;     // 64*RSTR

    const int tid  = threadIdx.x;
    const int w    = tid >> 5;
    const int lane = tid & 31;
    const int j0   = blockIdx.x * COLS;

    unsigned gen = g_flags[blockIdx.x];

    // weight fragments -> smem
    {
        const float* srcs[3] = { Wh, Vz, Vr };
        for (int g = 0; g < 3; g++) {
            const float* S = srcs[g];
            for (int idx = tid; idx < COLS * HH; idx += 256) {
                int j = idx >> 10, k = idx & 1023;
                float v = S[(j0 + j) * HH + k];
                int kk = k & 7;
                Bp[(g * 128 + (k >> 3)) * 64 + (j * 4 + (kk & 3)) * 2 + (kk >> 2)]
                    = __uint_as_float(cvt_tf32(v));
            }
        }
    }

    // ownership (threads 0..127): thread -> (jj in 0..7, batches b0..b0+3)
    const int jj = (tid & 127) >> 4;
    const int b0 = (tid & 15) * 4;
    const int kj = j0 + jj;
    const int pkk = kj & 7;
    const int pbi = b0 & 15;
    const int pbase = (((kj >> 7) * 4 + (b0 >> 4)) * 16 + ((kj >> 3) & 15)) * 128
                    + ((pbi & 7) * 4 + (pkk & 3)) * 4 + ((pbi >> 3) + 2 * (pkk >> 2));
    const bool owner = (tid < 128);

    float hst[4] = {0, 0, 0, 0}, zst[4] = {0, 0, 0, 0};

    if (owner) {
#pragma unroll
        for (int i = 0; i < 4; i++) __stcg(&g_hrP[pbase + i * 16], 0.0f);
    }
    gsync(++gen);

    const int c = lane & 3, q = lane >> 2;
    const int Abase = lane * 4;

    // preload x for t=0 (owners only)
    float4 xh4 = make_float4(0,0,0,0), xz4 = xh4, xr4 = xh4;
    if (owner) {
        const int xo = kj * BB + b0;
        xh4 = *(const float4*)&g_xh[xo];
        xz4 = *(const float4*)&g_xz[xo];
        xr4 = *(const float4*)&g_xr[xo];
    }

    for (int t = 0; t < TT; t++) {
        // ---------- phase 1: (h*r) @ Wh^T ----------
        float acc[4][4];
#pragma unroll
        for (int mt = 0; mt < 4; mt++)
#pragma unroll
            for (int r = 0; r < 4; r++) acc[mt][r] = 0.f;

#pragma unroll 4
        for (int ks = 0; ks < 16; ks++) {
            int kg = w * 16 + ks;
            float2 f0 = *(const float2*)&Bp[kg * 64 + lane * 2];
            unsigned bq[2] = { __float_as_uint(f0.x), __float_as_uint(f0.y) };
#pragma unroll
            for (int mt = 0; mt < 4; mt++) {
                float4 av = __ldcg((const float4*)&g_hrP[((w * 4 + mt) * 16 + ks) * 128 + Abase]);
                unsigned af[4] = { __float_as_uint(av.x), __float_as_uint(av.y),
                                   __float_as_uint(av.z), __float_as_uint(av.w) };
                mma8(acc[mt], af, bq);
            }
        }
        // reduce: 8 k-partials -> 4 (warps 4-7 add onto 0-3), then sum 4
        if (w < 4) {
#pragma unroll
            for (int mt = 0; mt < 4; mt++) {
                float* p = &redz[(w * 8 + 2 * c) * RSTR + mt * 16 + q];
                p[0] = acc[mt][0]; p[RSTR] = acc[mt][1];
                p[8] = acc[mt][2]; p[RSTR + 8] = acc[mt][3];
            }
        }
        __syncthreads();
        if (w >= 4) {
#pragma unroll
            for (int mt = 0; mt < 4; mt++) {
                float* p = &redz[((w - 4) * 8 + 2 * c) * RSTR + mt * 16 + q];
                p[0] += acc[mt][0]; p[RSTR] += acc[mt][1];
                p[8] += acc[mt][2]; p[RSTR + 8] += acc[mt][3];
            }
        }
        __syncthreads();
        if (owner) {
            float s[4] = {0, 0, 0, 0};
#pragma unroll
            for (int p4 = 0; p4 < 4; p4++) {
                float4 v = *(const float4*)&redz[(p4 * 8 + jj) * RSTR + b0];
                s[0] += v.x; s[1] += v.y; s[2] += v.z; s[3] += v.w;
            }
            float xv[4] = { xh4.x, xh4.y, xh4.z, xh4.w };
#pragma unroll
            for (int i = 0; i < 4; i++) {
                float ht = tanhf(xv[i] + s[i]);
                hst[i] = zst[i] * hst[i] + (1.f - zst[i]) * ht;
                __stcg(&g_hP[pbase + i * 16], __uint_as_float(cvt_tf32(hst[i])));
            }
            if (t == TT - 1)
                *(float4*)&g_hT[kj * BB + b0] = make_float4(hst[0], hst[1], hst[2], hst[3]);
        }
        gsync(++gen);

        // ---------- phase 2: h @ Vz^T and h @ Vr^T (fused) ----------
        float az[4][4], ar[4][4];
#pragma unroll
        for (int mt = 0; mt < 4; mt++)
#pragma unroll
            for (int r = 0; r < 4; r++) { az[mt][r] = 0.f; ar[mt][r] = 0.f; }

#pragma unroll 4
        for (int ks = 0; ks < 16; ks++) {
            int kg = w * 16 + ks;
            float2 zf = *(const float2*)&Bp[(128 + kg) * 64 + lane * 2];
            float2 rf = *(const float2*)&Bp[(256 + kg) * 64 + lane * 2];
            unsigned bz[2] = { __float_as_uint(zf.x), __float_as_uint(zf.y) };
            unsigned br[2] = { __float_as_uint(rf.x), __float_as_uint(rf.y) };
#pragma unroll
            for (int mt = 0; mt < 4; mt++) {
                float4 av = __ldcg((const float4*)&g_hP[((w * 4 + mt) * 16 + ks) * 128 + Abase]);
                unsigned af[4] = { __float_as_uint(av.x), __float_as_uint(av.y),
                                   __float_as_uint(av.z), __float_as_uint(av.w) };
                mma8(az[mt], af, bz);
                mma8(ar[mt], af, br);
            }
        }
        if (w < 4) {
#pragma unroll
            for (int mt = 0; mt < 4; mt++) {
                float* pz = &redz[(w * 8 + 2 * c) * RSTR + mt * 16 + q];
                float* pr = &redr[(w * 8 + 2 * c) * RSTR + mt * 16 + q];
                pz[0] = az[mt][0]; pz[RSTR] = az[mt][1]; pz[8] = az[mt][2]; pz[RSTR + 8] = az[mt][3];
                pr[0] = ar[mt][0]; pr[RSTR] = ar[mt][1]; pr[8] = ar[mt][2]; pr[RSTR + 8] = ar[mt][3];
            }
        }
        __syncthreads();
        if (w >= 4) {
#pragma unroll
            for (int mt = 0; mt < 4; mt++) {
                float* pz = &redz[((w - 4) * 8 + 2 * c) * RSTR + mt * 16 + q];
                float* pr = &redr[((w - 4) * 8 + 2 * c) * RSTR + mt * 16 + q];
                pz[0] += az[mt][0]; pz[RSTR] += az[mt][1]; pz[8] += az[mt][2]; pz[RSTR + 8] += az[mt][3];
                pr[0] += ar[mt][0]; pr[RSTR] += ar[mt][1]; pr[8] += ar[mt][2]; pr[RSTR + 8] += ar[mt][3];
            }
        }
        __syncthreads();
        if (owner) {
            float sz[4] = {0, 0, 0, 0}, sr[4] = {0, 0, 0, 0};
#pragma unroll
            for (int p4 = 0; p4 < 4; p4++) {
                float4 vz = *(const float4*)&redz[(p4 * 8 + jj) * RSTR + b0];
                float4 vr = *(const float4*)&redr[(p4 * 8 + jj) * RSTR + b0];
                sz[0] += vz.x; sz[1] += vz.y; sz[2] += vz.z; sz[3] += vz.w;
                sr[0] += vr.x; sr[1] += vr.y; sr[2] += vr.z; sr[3] += vr.w;
            }
            float zv[4] = { xz4.x, xz4.y, xz4.z, xz4.w };
            float rv[4] = { xr4.x, xr4.y, xr4.z, xr4.w };
#pragma unroll
            for (int i = 0; i < 4; i++) {
                zst[i] = sigm_(zv[i] + sz[i]);
                float ri = sigm_(rv[i] + sr[i]);
                __stcg(&g_hrP[pbase + i * 16], __uint_as_float(cvt_tf32(hst[i] * ri)));
            }
            // prefetch x for next step (hidden behind the barrier wait)
            int tn = (t + 1 < TT) ? t + 1 : t;
            const int xo = tn * (HH * BB) + kj * BB + b0;
            xh4 = *(const float4*)&g_xh[xo];
            xz4 = *(const float4*)&g_xz[xo];
            xr4 = *(const float4*)&g_xr[xo];
        }
        gsync(++gen);
    }
}

// -------- kernel 3: output projection --------
__global__ __launch_bounds__(256) void out_kernel(
    const float* __restrict__ Wo, const float* __restrict__ bo, float* __restrict__ out)
{
    const int b = threadIdx.x & 63;
    const int o = blockIdx.x * 4 + (threadIdx.x >> 6);
    float s = 0.f;
#pragma unroll 8
    for (int j = 0; j < HH; j++)
        s += g_hT[j * BB + b] * Wo[o * HH + j];
    out[b * OUTD + o] = s + bo[o];
}

extern "C" void kernel_launch(void* const* d_in, const int* in_sizes, int n_in,
                              void* d_out, int out_size) {
    const float* X  = (const float*)d_in[0];
    const float* Wx = (const float*)d_in[1];
    const float* bx = (const float*)d_in[2];
    const float* Wh = (const float*)d_in[3];
    const float* Uz = (const float*)d_in[4];
    const float* bz = (const float*)d_in[5];
    const float* Vz = (const float*)d_in[6];
    const float* Ur = (const float*)d_in[7];
    const float* br = (const float*)d_in[8];
    const float* Vr = (const float*)d_in[9];
    const float* Wo = (const float*)d_in[10];
    const float* bo = (const float*)d_in[11];
    float* out = (float*)d_out;

    const int scan_smem = (24576 + 2 * 64 * RSTR) * (int)sizeof(float);
    cudaFuncSetAttribute(scan_kernel, cudaFuncAttributeMaxDynamicSharedMemorySize, scan_smem);

    dim3 pg(HH / 64, TT, 3);
    proj_kernel<<<pg, 256>>>(X, Wx, Uz, Ur, bx, bz, br);
    scan_kernel<<<NCTA, 256, scan_smem>>>(Wh, Vz, Vr);
    out_kernel<<<OUTD / 4, 256>>>(Wo, bo, out);
}

// round 9
// speedup vs baseline: 1.3534x; 1.3534x over previous
#include <cuda_runtime.h>
#include <math.h>

#define BB   64
#define TT   512
#define IND  256
#define HH   1024
#define OUTD 256

#define NCTA 64
#define COLS 16
#define RSTR 76

// -------- device scratch --------
__device__ float g_xh[TT * BB * HH];      // [t][j][b]
__device__ float g_xz[TT * BB * HH];
__device__ float g_xr[TT * BB * HH];
__device__ float g_hP [2][HH * BB];       // h   fragment-packed, double-buffered
__device__ float g_hrP[2][HH * BB];       // h*r fragment-packed, double-buffered
__device__ float g_hT [HH * BB];          // plain [j][b], final step only
__device__ unsigned g_fh [NCTA];          // per-CTA "h published" counters
__device__ unsigned g_fhr[NCTA];          // per-CTA "hr published" counters

// -------- helpers --------
__device__ __forceinline__ unsigned cvt_tf32(float x) {
    unsigned r; asm("cvt.rna.tf32.f32 %0, %1;" : "=r"(r) : "f"(x)); return r;
}
__device__ __forceinline__ void mma8(float (&d)[4], const unsigned (&a)[4], const unsigned (&b)[2]) {
    asm volatile("mma.sync.aligned.m16n8k8.row.col.f32.tf32.tf32.f32 "
                 "{%0,%1,%2,%3}, {%4,%5,%6,%7}, {%8,%9}, {%0,%1,%2,%3};"
                 : "+f"(d[0]), "+f"(d[1]), "+f"(d[2]), "+f"(d[3])
                 : "r"(a[0]), "r"(a[1]), "r"(a[2]), "r"(a[3]), "r"(b[0]), "r"(b[1]));
}
__device__ __forceinline__ float sigm_(float x) { return 1.0f / (1.0f + __expf(-x)); }

__device__ __forceinline__ unsigned long long splat2(float x) {
    unsigned long long r; asm("mov.b64 %0, {%1, %1};" : "=l"(r) : "f"(x)); return r;
}
__device__ __forceinline__ unsigned long long pack2(float x, float y) {
    unsigned long long r; asm("mov.b64 %0, {%1, %2};" : "=l"(r) : "f"(x), "f"(y)); return r;
}
__device__ __forceinline__ void fma2(unsigned long long& d, unsigned long long a, unsigned long long b) {
    asm("fma.rn.f32x2 %0, %1, %2, %0;" : "+l"(d) : "l"(a), "l"(b));
}
__device__ __forceinline__ float2 unpack2(unsigned long long v) {
    float2 f; asm("mov.b64 {%0, %1}, %2;" : "=f"(f.x), "=f"(f.y) : "l"(v)); return f;
}

// -------- dataflow sync primitives --------
// Publish: after __syncthreads (CTA stores drained), thread 0 release-stores
// the counter. Consumers use ld.acquire + .cg data loads (L2 coherence point).
__device__ __forceinline__ void publish(unsigned* flag, unsigned val) {
    asm volatile("st.release.gpu.global.u32 [%0], %1;" :: "l"(flag), "r"(val) : "memory");
}
// Warp-collective wait: lanes poll flags[base + (lane&7)] (8 producers).
__device__ __forceinline__ void wait8(const unsigned* flags, int base, unsigned target) {
    const unsigned* p = flags + base + (threadIdx.x & 7);
    unsigned v;
    do {
        asm volatile("ld.acquire.gpu.global.u32 %0, [%1];" : "=r"(v) : "l"(p) : "memory");
    } while (!__all_sync(0xffffffffu, (int)(v - target) >= 0));
}

// -------- kernel 1: input projections --------
__global__ __launch_bounds__(256) void proj_kernel(
    const float* __restrict__ X,
    const float* __restrict__ W0, const float* __restrict__ W1, const float* __restrict__ W2,
    const float* __restrict__ b0, const float* __restrict__ b1, const float* __restrict__ b2)
{
    __shared__ float As[32][68];
    __shared__ float Bs[32][68];

    const int z = blockIdx.z;
    const float* W    = (z == 0) ? W0 : (z == 1) ? W1 : W2;
    const float* bias = (z == 0) ? b0 : (z == 1) ? b1 : b2;
    float*       outp = (z == 0) ? g_xh : (z == 1) ? g_xz : g_xr;

    const int t   = blockIdx.y;
    const int j0  = blockIdx.x * 64;
    const int tid = threadIdx.x;
    const int ty  = tid >> 4;
    const int tx  = tid & 15;

    unsigned long long acc2[4][2];
#pragma unroll
    for (int i = 0; i < 4; i++) { acc2[i][0] = 0ull; acc2[i][1] = 0ull; }

    for (int kt = 0; kt < IND; kt += 32) {
#pragma unroll
        for (int l = 0; l < 8; l++) {
            int flat = tid + l * 256;
            int row = flat >> 5, col = flat & 31;
            As[col][row] = W[(j0 + row) * IND + kt + col];
            Bs[col][row] = X[row * (TT * IND) + t * IND + kt + col];
        }
        __syncthreads();
#pragma unroll
        for (int kk = 0; kk < 32; kk++) {
            float4 a4 = *reinterpret_cast<const float4*>(&As[kk][ty * 4]);
            float4 b4 = *reinterpret_cast<const float4*>(&Bs[kk][tx * 4]);
            unsigned long long p01 = pack2(b4.x, b4.y);
            unsigned long long p23 = pack2(b4.z, b4.w);
            float a[4] = { a4.x, a4.y, a4.z, a4.w };
#pragma unroll
            for (int i = 0; i < 4; i++) {
                unsigned long long aa = splat2(a[i]);
                fma2(acc2[i][0], aa, p01);
                fma2(acc2[i][1], aa, p23);
            }
        }
        __syncthreads();
    }
#pragma unroll
    for (int i = 0; i < 4; i++) {
        int j = j0 + ty * 4 + i;
        float bvv = bias[j];
        float2 p0 = unpack2(acc2[i][0]);
        float2 p1 = unpack2(acc2[i][1]);
        float4 v = make_float4(p0.x + bvv, p0.y + bvv, p1.x + bvv, p1.y + bvv);
        *reinterpret_cast<float4*>(&outp[t * (HH * BB) + j * BB + tx * 4]) = v;
    }
}

// -------- cross-warp reduction (R6, known-good) --------
__device__ __forceinline__ void reduce16(float* red, const float (*a)[2][4],
                                         int w, int c, int q, int jj, int b0, float (&s)[4])
{
    if (w < 4) {
#pragma unroll
        for (int mt = 0; mt < 4; mt++)
#pragma unroll
            for (int nt = 0; nt < 2; nt++) {
                float* p = &red[(w * 16 + nt * 8 + 2 * c) * RSTR + mt * 16 + q];
                p[0] = a[mt][nt][0]; p[RSTR] = a[mt][nt][1];
                p[8] = a[mt][nt][2]; p[RSTR + 8] = a[mt][nt][3];
            }
    }
    __syncthreads();
    if (w >= 4) {
#pragma unroll
        for (int mt = 0; mt < 4; mt++)
#pragma unroll
            for (int nt = 0; nt < 2; nt++) {
                float* p = &red[((w - 4) * 16 + nt * 8 + 2 * c) * RSTR + mt * 16 + q];
                p[0] += a[mt][nt][0]; p[RSTR] += a[mt][nt][1];
                p[8] += a[mt][nt][2]; p[RSTR + 8] += a[mt][nt][3];
            }
    }
    __syncthreads();
    s[0] = s[1] = s[2] = s[3] = 0.f;
#pragma unroll
    for (int p4 = 0; p4 < 4; p4++) {
        float4 v = *(const float4*)&red[(p4 * 16 + jj) * RSTR + b0];
        s[0] += v.x; s[1] += v.y; s[2] += v.z; s[3] += v.w;
    }
}

// -------- kernel 2: persistent scan (tf32 mma + dataflow flags) --------
__global__ __launch_bounds__(256, 1) void scan_kernel(
    const float* __restrict__ Wh, const float* __restrict__ Vz, const float* __restrict__ Vr)
{
    extern __shared__ float smem[];
    float* Bp  = smem;            // 3*128*2*64 floats (tf32 weight frags)
    float* red = smem + 49152;    // 4*16*RSTR floats

    const int tid  = threadIdx.x;
    const int w    = tid >> 5;
    const int lane = tid & 31;
    const int j0   = blockIdx.x * COLS;

    // settled flag bases (own flags: stable until we write them; all CTAs equal)
    const unsigned F0h  = g_fh [blockIdx.x];
    const unsigned F0hr = g_fhr[blockIdx.x];

    // weight fragments -> smem
    {
        const float* srcs[3] = { Wh, Vz, Vr };
        for (int g = 0; g < 3; g++) {
            const float* S = srcs[g];
            for (int idx = tid; idx < COLS * HH; idx += 256) {
                int j = idx >> 10, k = idx & 1023;
                float v = S[(j0 + j) * HH + k];
                int ksg = k >> 3, kk = k & 7;
                Bp[((g * 128 + ksg) * 2 + (j >> 3)) * 64 + ((j & 7) * 4 + (kk & 3)) * 2 + (kk >> 2)]
                    = __uint_as_float(cvt_tf32(v));
            }
        }
    }

    const int jj = tid >> 4;
    const int b0 = (tid & 15) * 4;
    const int kj = j0 + jj;
    const int pkk = kj & 7;
    const int pbi = b0 & 15;
    const int pbase = (((kj >> 7) * 4 + (b0 >> 4)) * 16 + ((kj >> 3) & 15)) * 128
                    + ((pbi & 7) * 4 + (pkk & 3)) * 4 + ((pbi >> 3) + 2 * (pkk >> 2));

    float hst[4] = {0, 0, 0, 0}, zst[4] = {0, 0, 0, 0};

    // init hr@-1 = 0 into buffer 1, publish
#pragma unroll
    for (int i = 0; i < 4; i++) __stcg(&g_hrP[1][pbase + i * 16], 0.0f);
    __syncthreads();
    if (tid == 0) publish(&g_fhr[blockIdx.x], F0hr + 1);

    const int c = lane & 3, q = lane >> 2;
    const int Abase = lane * 4;
    const int prodbase = w * 8;      // this warp's 8 producer CTAs

    for (int t = 0; t < TT; t++) {
        // x loads issued before the wait (latency hidden behind polling)
        const int xo = t * (HH * BB) + kj * BB + b0;
        float4 xh4 = *(const float4*)&g_xh[xo];
        float4 xz4 = *(const float4*)&g_xz[xo];
        float4 xr4 = *(const float4*)&g_xr[xo];

        // ---------- phase 1: (h*r) @ Wh^T ----------
        wait8(g_fhr, prodbase, F0hr + 1 + t);     // hr@(t-1) available
        const float* hrbuf = g_hrP[(t + 1) & 1];  // == (t-1)&1

        float acc[4][2][4];
#pragma unroll
        for (int mt = 0; mt < 4; mt++)
#pragma unroll
            for (int nt = 0; nt < 2; nt++)
#pragma unroll
                for (int r = 0; r < 4; r++) acc[mt][nt][r] = 0.f;

#pragma unroll 4
        for (int ks = 0; ks < 16; ks++) {
            int kg = w * 16 + ks;
            float2 f0 = *(const float2*)&Bp[(kg * 2 + 0) * 64 + lane * 2];
            float2 f1 = *(const float2*)&Bp[(kg * 2 + 1) * 64 + lane * 2];
            unsigned bq0[2] = { __float_as_uint(f0.x), __float_as_uint(f0.y) };
            unsigned bq1[2] = { __float_as_uint(f1.x), __float_as_uint(f1.y) };
#pragma unroll
            for (int mt = 0; mt < 4; mt++) {
                float4 av = __ldcg((const float4*)&hrbuf[((w * 4 + mt) * 16 + ks) * 128 + Abase]);
                unsigned af[4] = { __float_as_uint(av.x), __float_as_uint(av.y),
                                   __float_as_uint(av.z), __float_as_uint(av.w) };
                mma8(acc[mt][0], af, bq0);
                mma8(acc[mt][1], af, bq1);
            }
        }
        {
            float s[4];
            reduce16(red, acc, w, c, q, jj, b0, s);
            float xv[4] = { xh4.x, xh4.y, xh4.z, xh4.w };
            float* hbuf = g_hP[t & 1];
#pragma unroll
            for (int i = 0; i < 4; i++) {
                float ht = tanhf(xv[i] + s[i]);
                hst[i] = zst[i] * hst[i] + (1.f - zst[i]) * ht;
                __stcg(&hbuf[pbase + i * 16], __uint_as_float(cvt_tf32(hst[i])));
            }
            if (t == TT - 1)
                *(float4*)&g_hT[kj * BB + b0] = make_float4(hst[0], hst[1], hst[2], hst[3]);
        }
        __syncthreads();
        if (tid == 0) publish(&g_fh[blockIdx.x], F0h + 1 + t);

        // ---------- phase 2: h @ Vz^T and h @ Vr^T ----------
        wait8(g_fh, prodbase, F0h + 1 + t);       // h@t available
        const float* hbufr = g_hP[t & 1];

        float az[4][2][4], ar[4][2][4];
#pragma unroll
        for (int mt = 0; mt < 4; mt++)
#pragma unroll
            for (int nt = 0; nt < 2; nt++)
#pragma unroll
                for (int r = 0; r < 4; r++) { az[mt][nt][r] = 0.f; ar[mt][nt][r] = 0.f; }

#pragma unroll 4
        for (int ks = 0; ks < 16; ks++) {
            int kg = w * 16 + ks;
            float2 zf0 = *(const float2*)&Bp[((128 + kg) * 2 + 0) * 64 + lane * 2];
            float2 zf1 = *(const float2*)&Bp[((128 + kg) * 2 + 1) * 64 + lane * 2];
            float2 rf0 = *(const float2*)&Bp[((256 + kg) * 2 + 0) * 64 + lane * 2];
            float2 rf1 = *(const float2*)&Bp[((256 + kg) * 2 + 1) * 64 + lane * 2];
            unsigned bz0[2] = { __float_as_uint(zf0.x), __float_as_uint(zf0.y) };
            unsigned bz1[2] = { __float_as_uint(zf1.x), __float_as_uint(zf1.y) };
            unsigned br0[2] = { __float_as_uint(rf0.x), __float_as_uint(rf0.y) };
            unsigned br1[2] = { __float_as_uint(rf1.x), __float_as_uint(rf1.y) };
#pragma unroll
            for (int mt = 0; mt < 4; mt++) {
                float4 av = __ldcg((const float4*)&hbufr[((w * 4 + mt) * 16 + ks) * 128 + Abase]);
                unsigned af[4] = { __float_as_uint(av.x), __float_as_uint(av.y),
                                   __float_as_uint(av.z), __float_as_uint(av.w) };
                mma8(az[mt][0], af, bz0);
                mma8(az[mt][1], af, bz1);
                mma8(ar[mt][0], af, br0);
                mma8(ar[mt][1], af, br1);
            }
        }
        {
            float sz[4], sr[4];
            reduce16(red, az, w, c, q, jj, b0, sz);
            __syncthreads();
            reduce16(red, ar, w, c, q, jj, b0, sr);
            float zv[4] = { xz4.x, xz4.y, xz4.z, xz4.w };
            float rv[4] = { xr4.x, xr4.y, xr4.z, xr4.w };
            float* hrw = g_hrP[t & 1];
#pragma unroll
            for (int i = 0; i < 4; i++) {
                zst[i] = sigm_(zv[i] + sz[i]);
                float ri = sigm_(rv[i] + sr[i]);
                __stcg(&hrw[pbase + i * 16], __uint_as_float(cvt_tf32(hst[i] * ri)));
            }
        }
        __syncthreads();
        if (tid == 0) publish(&g_fhr[blockIdx.x], F0hr + 2 + t);
    }
}

// -------- kernel 3: output projection --------
__global__ __launch_bounds__(256) void out_kernel(
    const float* __restrict__ Wo, const float* __restrict__ bo, float* __restrict__ out)
{
    const int b = threadIdx.x & 63;
    const int o = blockIdx.x * 4 + (threadIdx.x >> 6);
    float s = 0.f;
#pragma unroll 8
    for (int j = 0; j < HH; j++)
        s += g_hT[j * BB + b] * Wo[o * HH + j];
    out[b * OUTD + o] = s + bo[o];
}

extern "C" void kernel_launch(void* const* d_in, const int* in_sizes, int n_in,
                              void* d_out, int out_size) {
    const float* X  = (const float*)d_in[0];
    const float* Wx = (const float*)d_in[1];
    const float* bx = (const float*)d_in[2];
    const float* Wh = (const float*)d_in[3];
    const float* Uz = (const float*)d_in[4];
    const float* bz = (const float*)d_in[5];
    const float* Vz = (const float*)d_in[6];
    const float* Ur = (const float*)d_in[7];
    const float* br = (const float*)d_in[8];
    const float* Vr = (const float*)d_in[9];
    const float* Wo = (const float*)d_in[10];
    const float* bo = (const float*)d_in[11];
    float* out = (float*)d_out;

    const int scan_smem = (49152 + 4 * 16 * RSTR) * (int)sizeof(float);
    cudaFuncSetAttribute(scan_kernel, cudaFuncAttributeMaxDynamicSharedMemorySize, scan_smem);

    dim3 pg(HH / 64, TT, 3);
    proj_kernel<<<pg, 256>>>(X, Wx, Uz, Ur, bx, bz, br);
    scan_kernel<<<NCTA, 256, scan_smem>>>(Wh, Vz, Vr);
    out_kernel<<<OUTD / 4, 256>>>(Wo, bo, out);
}